// round 8
// baseline (speedup 1.0000x reference)
#include <cuda_runtime.h>
#include <cuda_bf16.h>
#include <cstddef>

// Problem constants
#define NB    2
#define SLEN  2048
#define EMB   1024            // H=16, D=64
#define NBLK  128             // persistent grid: 1 block/SM, uniform placement
#define THR   1024
#define CPN   64              // partial chunks per batch (32 rows each)

// Scratch (__device__ globals; no allocation). Zero-init counters/flags;
// the last exiting block resets them -> graph-replay safe.
__device__ float g_part[NB][CPN][EMB];  // per-chunk column-sum partials (512 KB)
__device__ float g_t[NB][EMB];          // t = blockdiag(Wv) @ sv
__device__ float g_y[NB][EMB];          // y = Wo @ t + bo
__device__ int   g_c1, g_c2, g_c3, g_ce;
__device__ volatile int g_f1, g_f2, g_f3;

// Grid-wide barrier: arrive (ticket), last sets flag, rest spin (tid 0 only).
__device__ __forceinline__ void gbar(int* cnt, volatile int* flag)
{
    __syncthreads();
    if (threadIdx.x == 0) {
        __threadfence();                       // publish this block's writes
        if (atomicAdd(cnt, 1) == NBLK - 1) {
            *flag = 1;
        } else {
            while (*flag == 0) { __nanosleep(32); }
        }
        __threadfence();
    }
    __syncthreads();
}

__global__ void __launch_bounds__(THR, 1)
k_fused(const float* __restrict__ vals,
        const float* __restrict__ Wv,
        const float* __restrict__ Wo,
        const float* __restrict__ bo,
        float*       __restrict__ out)
{
    const int b   = blockIdx.x;
    const int tid = threadIdx.x;

    __shared__ float4 s_red[4][256];   // P1 rowgroup combine (16 KB)

    // ======================= P1: column-sum partials =======================
    // Block b: batch n = b>>6, 32-row slab c = b&63. 4 rowgroups x 256 cols;
    // each thread sums 8 rows (MLP=8), then smem-combine -> ONE 4KB partial.
    {
        const int n   = b >> 6;
        const int c   = b & 63;
        const int rg  = tid >> 8;      // rowgroup 0..3 (8 rows each)
        const int col = tid & 255;     // float4 lane over EMB

        const float4* __restrict__ base =
            (const float4*)(vals + (size_t)(n * SLEN + c * 32 + rg * 8) * EMB);

        float4 acc = make_float4(0.f, 0.f, 0.f, 0.f);
        #pragma unroll
        for (int s = 0; s < 8; ++s) {
            float4 v = __ldg(&base[s * (EMB / 4) + col]);
            acc.x += v.x; acc.y += v.y; acc.z += v.z; acc.w += v.w;
        }
        s_red[rg][col] = acc;
        __syncthreads();
        if (tid < 256) {
            float4 a0 = s_red[0][tid], a1 = s_red[1][tid];
            float4 a2 = s_red[2][tid], a3 = s_red[3][tid];
            a0.x = (a0.x + a1.x) + (a2.x + a3.x);
            a0.y = (a0.y + a1.y) + (a2.y + a3.y);
            a0.z = (a0.z + a1.z) + (a2.z + a3.z);
            a0.w = (a0.w + a1.w) + (a2.w + a3.w);
            ((float4*)g_part[n][c])[tid] = a0;
        }
    }
    gbar(&g_c1, &g_f1);

    // ================= P2: reduce partials -> sv, apply Wv =================
    // 32 blocks: (n = b>>4, head h = b&15). 1024 threads = 64 chunks x 16
    // float4 cols; fixed-pairing smem tree (deterministic). Then 64-thread
    // Wv matvec for this head.
    if (b < 32) {
        const int n = b >> 4;
        const int h = b & 15;
        const int c = tid >> 4;        // chunk 0..63
        const int L = tid & 15;        // float4 col within the head

        __shared__ float4 sp[64][16];
        sp[c][L] = __ldcg(&((const float4*)g_part[n][c])[h * 16 + L]);
        __syncthreads();
        #pragma unroll
        for (int st = 32; st >= 1; st >>= 1) {
            if (c < st) {
                float4 a = sp[c][L], d = sp[c + st][L];
                a.x += d.x; a.y += d.y; a.z += d.z; a.w += d.w;
                sp[c][L] = a;
            }
            __syncthreads();
        }
        if (tid < 64) {
            const float* __restrict__ svh  = (const float*)sp[0];  // 64 floats
            const float* __restrict__ wrow = Wv + tid * 64;
            float acc = 0.f;
            #pragma unroll 16
            for (int dp = 0; dp < 64; ++dp) acc += __ldg(&wrow[dp]) * svh[dp];
            g_t[n][h * 64 + tid] = acc;
        }
    }
    gbar(&g_c2, &g_f2);

    // ===================== P3: y = Wo @ t + bo (both n) =====================
    // 128 blocks x 8 e-rows; 4 warps per e split the 1024-wide dot (quarters).
    {
        const int e0   = b * 8;
        const int w    = tid >> 5;       // warp 0..31
        const int lane = tid & 31;
        const int el   = w >> 2;         // e-local 0..7
        const int q    = w & 3;          // quarter (64 float4 each)

        const int e = e0 + el;
        const float4* __restrict__ row =
            (const float4*)(Wo + (size_t)e * EMB) + q * 64;
        const float4* __restrict__ t0 = (const float4*)g_t[0] + q * 64;
        const float4* __restrict__ t1 = (const float4*)g_t[1] + q * 64;

        float a0 = 0.f, a1 = 0.f;
        #pragma unroll
        for (int i = lane; i < 64; i += 32) {
            float4 wv = __ldg(&row[i]);
            float4 x  = __ldcg(&t0[i]);
            float4 z  = __ldcg(&t1[i]);
            a0 += wv.x * x.x + wv.y * x.y + wv.z * x.z + wv.w * x.w;
            a1 += wv.x * z.x + wv.y * z.y + wv.z * z.z + wv.w * z.w;
        }
        #pragma unroll
        for (int o = 16; o; o >>= 1) {
            a0 += __shfl_xor_sync(0xFFFFFFFFu, a0, o);
            a1 += __shfl_xor_sync(0xFFFFFFFFu, a1, o);
        }

        __shared__ float s_part[NB][8][4];
        if (lane == 0) {
            s_part[0][el][q] = a0;
            s_part[1][el][q] = a1;
        }
        __syncthreads();
        if (tid < 16) {                   // n = tid>>3, e-local = tid&7
            const int nn = tid >> 3;
            const int ee = tid & 7;
            g_y[nn][e0 + ee] = ((s_part[nn][ee][0] + s_part[nn][ee][1])
                              + (s_part[nn][ee][2] + s_part[nn][ee][3]))
                             + __ldg(&bo[e0 + ee]);
        }
    }
    gbar(&g_c3, &g_f3);

    // ===================== P4: broadcast y to all rows =====================
    // Block b: batch n = b>>6, 32-row slab; rowgroup writes 8 rows.
    {
        const int n   = b >> 6;
        const int c   = b & 63;
        const int rg  = tid >> 8;
        const int col = tid & 255;
        const float4 v = __ldcg(&((const float4*)g_y[n])[col]);

        float4* __restrict__ dst =
            (float4*)(out + (size_t)(n * SLEN + c * 32 + rg * 8) * EMB);
        #pragma unroll
        for (int s = 0; s < 8; ++s)
            dst[s * (EMB / 4) + col] = v;
    }

    // ======================= exit: reset for replay ========================
    __threadfence();
    __syncthreads();
    if (tid == 0) {
        if (atomicAdd(&g_ce, 1) == NBLK - 1) {
            g_c1 = 0; g_c2 = 0; g_c3 = 0; g_ce = 0;
            g_f1 = 0; g_f2 = 0; g_f3 = 0;
        }
    }
}

// ---------------------------------------------------------------------------
// Inputs (metadata order): 0=values 1=keys 2=queries 3=mask 4=Wv 5=Wk 6=Wq
//                          7=Wo 8=bo.   Output: float32 [2, 2048, 1024].
// ---------------------------------------------------------------------------
extern "C" void kernel_launch(void* const* d_in, const int* in_sizes, int n_in,
                              void* d_out, int out_size)
{
    const float* values = (const float*)d_in[0];
    const float* Wv     = (const float*)d_in[4];
    const float* Wo     = (const float*)d_in[7];
    const float* bo     = (const float*)d_in[8];
    float*       out    = (float*)d_out;

    k_fused<<<NBLK, THR>>>(values, Wv, Wo, bo, out);
}

// round 9
// speedup vs baseline: 1.0015x; 1.0015x over previous
#include <cuda_runtime.h>
#include <cuda_bf16.h>
#include <cstddef>
#include <cstdint>

// Problem constants
#define NB    2
#define SLEN  2048
#define EMB   1024            // H=16, D=64
#define NBLK  128             // persistent grid: 1 block/SM, uniform placement
#define THR   1024
#define CPN   64              // partial chunks per batch (32 rows each)

// Scratch (__device__ globals; no allocation). Zero-init counters/flags;
// the last exiting block resets them -> graph-replay safe.
__device__ float g_part[NB][CPN][EMB];  // per-chunk column-sum partials (512 KB)
__device__ float g_t[NB][EMB];          // t = blockdiag(Wv) @ sv
__device__ float g_y[NB][EMB];          // y = Wo @ t + bo
__device__ int   g_c1, g_c2, g_c3, g_ce;
__device__ volatile int g_f1, g_f2, g_f3;

// ---- PTX helpers: mbarrier + cp.async.bulk (non-tensor TMA path) ----------
__device__ __forceinline__ void mbar_init(uint32_t mb, uint32_t cnt) {
    asm volatile("mbarrier.init.shared.b64 [%0], %1;" :: "r"(mb), "r"(cnt) : "memory");
}
__device__ __forceinline__ void mbar_expect_tx(uint32_t mb, uint32_t bytes) {
    asm volatile("mbarrier.arrive.expect_tx.shared.b64 _, [%0], %1;"
                 :: "r"(mb), "r"(bytes) : "memory");
}
__device__ __forceinline__ void bulk_ld(uint32_t sdst, const void* gsrc,
                                        uint32_t bytes, uint32_t mb) {
    asm volatile(
        "cp.async.bulk.shared::cta.global.mbarrier::complete_tx::bytes [%0], [%1], %2, [%3];"
        :: "r"(sdst), "l"(gsrc), "r"(bytes), "r"(mb) : "memory");
}
__device__ __forceinline__ void bulk_st(void* gdst, uint32_t ssrc, uint32_t bytes) {
    asm volatile("cp.async.bulk.global.shared::cta.bulk_group [%0], [%1], %2;"
                 :: "l"(gdst), "r"(ssrc), "r"(bytes) : "memory");
}
__device__ __forceinline__ void mbar_wait(uint32_t mb, uint32_t parity) {
    uint32_t done;
    asm volatile(
        "{\n .reg .pred p;\n"
        " mbarrier.try_wait.parity.acquire.cta.shared::cta.b64 p, [%1], %2;\n"
        " selp.b32 %0, 1, 0, p;\n}"
        : "=r"(done) : "r"(mb), "r"(parity) : "memory");
    while (!done) {
        asm volatile(
            "{\n .reg .pred p;\n"
            " mbarrier.try_wait.parity.acquire.cta.shared::cta.b64 p, [%1], %2, 0x989680;\n"
            " selp.b32 %0, 1, 0, p;\n}"
            : "=r"(done) : "r"(mb), "r"(parity) : "memory");
    }
}

// Grid-wide barrier: arrive (ticket), last sets flag, rest spin (tid 0 only).
__device__ __forceinline__ void gbar(int* cnt, volatile int* flag)
{
    __syncthreads();
    if (threadIdx.x == 0) {
        __threadfence();                       // publish this block's writes
        if (atomicAdd(cnt, 1) == NBLK - 1) {
            *flag = 1;
        } else {
            while (*flag == 0) { __nanosleep(32); }
        }
        __threadfence();
    }
    __syncthreads();
}

__global__ void __launch_bounds__(THR, 1)
k_fused(const float* __restrict__ vals,
        const float* __restrict__ Wv,
        const float* __restrict__ Wo,
        const float* __restrict__ bo,
        float*       __restrict__ out)
{
    const int b   = blockIdx.x;
    const int tid = threadIdx.x;

    __shared__ __align__(128) float s_pool[8192];   // 32 KB overlay (all phases)
    __shared__ uint64_t s_mbar[2];
    __shared__ float s_part3[NB][8][4];

    const uint32_t sbuf = (uint32_t)__cvta_generic_to_shared(s_pool);
    const uint32_t mb0  = (uint32_t)__cvta_generic_to_shared(&s_mbar[0]);
    const uint32_t mb1  = (uint32_t)__cvta_generic_to_shared(&s_mbar[1]);

    // ======================= P1: column-sum partials =======================
    // Block b: batch n = b>>6, 32-row slab c = b&63 (128 KB). Stream via
    // 8 x 16 KB bulk loads (double-buffered mbarrier pipeline); accumulate
    // from SMEM; rowgroup-combine -> one 4 KB partial.
    {
        const int n = b >> 6;
        const int c = b & 63;
        const float* __restrict__ slab = vals + (size_t)(n * SLEN + c * 32) * EMB;

        if (tid == 0) { mbar_init(mb0, 1); mbar_init(mb1, 1); }
        __syncthreads();
        if (tid == 0) { mbar_expect_tx(mb0, 16384); bulk_ld(sbuf, slab, 16384, mb0); }

        float4 acc = make_float4(0.f, 0.f, 0.f, 0.f);
        #pragma unroll
        for (int s = 0; s < 8; ++s) {
            if (tid == 0 && s < 7) {
                const uint32_t mbn = ((s + 1) & 1) ? mb1 : mb0;
                mbar_expect_tx(mbn, 16384);
                bulk_ld(sbuf + ((s + 1) & 1) * 16384, slab + (s + 1) * 4096,
                        16384, mbn);
            }
            mbar_wait((s & 1) ? mb1 : mb0, (s >> 1) & 1);
            const float4 v = ((const float4*)s_pool)[(s & 1) * 1024 + tid];
            acc.x += v.x; acc.y += v.y; acc.z += v.z; acc.w += v.w;
            __syncthreads();           // everyone done reading before buffer reuse
        }
        // rowgroup combine: thread = (rg = tid>>8, col = tid&255) -> index tid
        ((float4*)s_pool)[tid] = acc;
        __syncthreads();
        if (tid < 256) {
            float4 a0 = ((const float4*)s_pool)[tid];
            const float4 a1 = ((const float4*)s_pool)[256 + tid];
            const float4 a2 = ((const float4*)s_pool)[512 + tid];
            const float4 a3 = ((const float4*)s_pool)[768 + tid];
            a0.x = (a0.x + a1.x) + (a2.x + a3.x);
            a0.y = (a0.y + a1.y) + (a2.y + a3.y);
            a0.z = (a0.z + a1.z) + (a2.z + a3.z);
            a0.w = (a0.w + a1.w) + (a2.w + a3.w);
            ((float4*)g_part[n][c])[tid] = a0;
        }
    }
    gbar(&g_c1, &g_f1);

    // ================= P2: reduce partials -> sv, apply Wv =================
    // 32 blocks: (n = b>>4, head h = b&15). 1024 threads = 64 chunks x 16
    // float4 cols; fixed-pairing smem tree. Then 64-thread Wv matvec.
    if (b < 32) {
        const int n = b >> 4;
        const int h = b & 15;
        const int c = tid >> 4;        // chunk 0..63
        const int L = tid & 15;        // float4 col within the head

        float4* sp = (float4*)s_pool;  // [64][16]
        sp[c * 16 + L] = __ldcg(&((const float4*)g_part[n][c])[h * 16 + L]);
        __syncthreads();
        #pragma unroll
        for (int st = 32; st >= 1; st >>= 1) {
            if (c < st) {
                float4 a = sp[c * 16 + L], d2 = sp[(c + st) * 16 + L];
                a.x += d2.x; a.y += d2.y; a.z += d2.z; a.w += d2.w;
                sp[c * 16 + L] = a;
            }
            __syncthreads();
        }
        if (tid < 64) {
            const float* __restrict__ svh  = (const float*)s_pool;  // 64 floats
            const float* __restrict__ wrow = Wv + tid * 64;
            float acc = 0.f;
            #pragma unroll 16
            for (int dp = 0; dp < 64; ++dp) acc += __ldg(&wrow[dp]) * svh[dp];
            g_t[n][h * 64 + tid] = acc;
        }
    }
    gbar(&g_c2, &g_f2);

    // ===================== P3: y = Wo @ t + bo (both n) =====================
    // 128 blocks x 8 e-rows; 4 warps per e split the 1024-wide dot.
    {
        const int e0   = b * 8;
        const int w    = tid >> 5;       // warp 0..31
        const int lane = tid & 31;
        const int el   = w >> 2;         // e-local 0..7
        const int q    = w & 3;          // quarter (64 float4 each)

        const int e = e0 + el;
        const float4* __restrict__ row =
            (const float4*)(Wo + (size_t)e * EMB) + q * 64;
        const float4* __restrict__ t0 = (const float4*)g_t[0] + q * 64;
        const float4* __restrict__ t1 = (const float4*)g_t[1] + q * 64;

        float a0 = 0.f, a1 = 0.f;
        #pragma unroll
        for (int i = lane; i < 64; i += 32) {
            float4 wv = __ldg(&row[i]);
            float4 x  = __ldcg(&t0[i]);
            float4 z  = __ldcg(&t1[i]);
            a0 += wv.x * x.x + wv.y * x.y + wv.z * x.z + wv.w * x.w;
            a1 += wv.x * z.x + wv.y * z.y + wv.z * z.z + wv.w * z.w;
        }
        #pragma unroll
        for (int o = 16; o; o >>= 1) {
            a0 += __shfl_xor_sync(0xFFFFFFFFu, a0, o);
            a1 += __shfl_xor_sync(0xFFFFFFFFu, a1, o);
        }
        if (lane == 0) {
            s_part3[0][el][q] = a0;
            s_part3[1][el][q] = a1;
        }
        __syncthreads();
        if (tid < 16) {                   // n = tid>>3, e-local = tid&7
            const int nn = tid >> 3;
            const int ee = tid & 7;
            g_y[nn][e0 + ee] = ((s_part3[nn][ee][0] + s_part3[nn][ee][1])
                              + (s_part3[nn][ee][2] + s_part3[nn][ee][3]))
                             + __ldg(&bo[e0 + ee]);
        }
    }
    gbar(&g_c3, &g_f3);

    // ===================== P4: broadcast y to all rows =====================
    // Replicate y 8x in SMEM (32 KB), then 4 x 32 KB bulk stores per block.
    {
        const int n = b >> 6;
        const int c = b & 63;

        const float4 vy = __ldcg(&((const float4*)g_y[n])[tid & 255]);
        ((float4*)s_pool)[tid]        = vy;   // reps 0..3
        ((float4*)s_pool)[1024 + tid] = vy;   // reps 4..7
        asm volatile("fence.proxy.async.shared::cta;" ::: "memory");
        __syncthreads();

        if (tid == 0) {
            float* dst = out + (size_t)(n * SLEN + c * 32) * EMB;
            #pragma unroll
            for (int r = 0; r < 4; ++r)
                bulk_st(dst + r * 8192, sbuf, 32768);
            asm volatile("cp.async.bulk.commit_group;" ::: "memory");
            asm volatile("cp.async.bulk.wait_group 0;" ::: "memory");
        }
    }

    // ======================= exit: reset for replay ========================
    __threadfence();
    __syncthreads();
    if (tid == 0) {
        if (atomicAdd(&g_ce, 1) == NBLK - 1) {
            g_c1 = 0; g_c2 = 0; g_c3 = 0; g_ce = 0;
            g_f1 = 0; g_f2 = 0; g_f3 = 0;
        }
    }
}

// ---------------------------------------------------------------------------
// Inputs (metadata order): 0=values 1=keys 2=queries 3=mask 4=Wv 5=Wk 6=Wq
//                          7=Wo 8=bo.   Output: float32 [2, 2048, 1024].
// ---------------------------------------------------------------------------
extern "C" void kernel_launch(void* const* d_in, const int* in_sizes, int n_in,
                              void* d_out, int out_size)
{
    const float* values = (const float*)d_in[0];
    const float* Wv     = (const float*)d_in[4];
    const float* Wo     = (const float*)d_in[7];
    const float* bo     = (const float*)d_in[8];
    float*       out    = (float*)d_out;

    k_fused<<<NBLK, THR>>>(values, Wv, Wo, bo, out);
}

// round 10
// speedup vs baseline: 1.0107x; 1.0091x over previous
#include <cuda_runtime.h>
#include <cuda_bf16.h>
#include <cstddef>
#include <cstdint>

// Problem constants
#define NB    2
#define SLEN  2048
#define EMB   1024            // H=16, D=64
#define NBLK  128             // persistent grid: 1 block/SM, uniform placement
#define THR   1024
#define CPN   64              // partial chunks per batch (32 rows each)
#define SLAB_BYTES  131072    // 32 rows x 4 KB
#define SMEM_BYTES  (SLAB_BYTES + 256)

// Scratch (__device__ globals; no allocation). Zero-init counters/flags;
// the last exiting block resets them -> graph-replay safe.
__device__ float g_part[NB][CPN][EMB];  // per-chunk column-sum partials (512 KB)
__device__ float g_t[NB][EMB];          // t = blockdiag(Wv) @ sv
__device__ float g_y[NB][EMB];          // y = Wo @ t + bo
__device__ int   g_c1, g_c2, g_c3, g_ce;
__device__ volatile int g_f1, g_f2, g_f3;

// ---- PTX helpers: mbarrier + cp.async.bulk --------------------------------
__device__ __forceinline__ void mbar_init(uint32_t mb, uint32_t cnt) {
    asm volatile("mbarrier.init.shared.b64 [%0], %1;" :: "r"(mb), "r"(cnt) : "memory");
}
__device__ __forceinline__ void mbar_expect_tx(uint32_t mb, uint32_t bytes) {
    asm volatile("mbarrier.arrive.expect_tx.shared.b64 _, [%0], %1;"
                 :: "r"(mb), "r"(bytes) : "memory");
}
__device__ __forceinline__ void bulk_ld(uint32_t sdst, const void* gsrc,
                                        uint32_t bytes, uint32_t mb) {
    asm volatile(
        "cp.async.bulk.shared::cta.global.mbarrier::complete_tx::bytes [%0], [%1], %2, [%3];"
        :: "r"(sdst), "l"(gsrc), "r"(bytes), "r"(mb) : "memory");
}
__device__ __forceinline__ void bulk_st(void* gdst, uint32_t ssrc, uint32_t bytes) {
    asm volatile("cp.async.bulk.global.shared::cta.bulk_group [%0], [%1], %2;"
                 :: "l"(gdst), "r"(ssrc), "r"(bytes) : "memory");
}
__device__ __forceinline__ void mbar_wait(uint32_t mb, uint32_t parity) {
    uint32_t done;
    asm volatile(
        "{\n .reg .pred p;\n"
        " mbarrier.try_wait.parity.acquire.cta.shared::cta.b64 p, [%1], %2;\n"
        " selp.b32 %0, 1, 0, p;\n}"
        : "=r"(done) : "r"(mb), "r"(parity) : "memory");
    while (!done) {
        asm volatile(
            "{\n .reg .pred p;\n"
            " mbarrier.try_wait.parity.acquire.cta.shared::cta.b64 p, [%1], %2, 0x989680;\n"
            " selp.b32 %0, 1, 0, p;\n}"
            : "=r"(done) : "r"(mb), "r"(parity) : "memory");
    }
}

// Grid-wide barrier: arrive (ticket), last sets flag, rest spin (tid 0 only).
__device__ __forceinline__ void gbar(int* cnt, volatile int* flag)
{
    __syncthreads();
    if (threadIdx.x == 0) {
        __threadfence();                       // publish this block's writes
        if (atomicAdd(cnt, 1) == NBLK - 1) {
            *flag = 1;
        } else {
            while (*flag == 0) { __nanosleep(32); }
        }
        __threadfence();
    }
    __syncthreads();
}

__global__ void __launch_bounds__(THR, 1)
k_fused(const float* __restrict__ vals,
        const float* __restrict__ Wv,
        const float* __restrict__ Wo,
        const float* __restrict__ bo,
        float*       __restrict__ out)
{
    extern __shared__ __align__(128) float4 s_dyn[];   // 128 KB slab
    __shared__ uint64_t s_mbar;
    __shared__ float s_part3[NB][8][4];

    const int b   = blockIdx.x;
    const int tid = threadIdx.x;
    const uint32_t sbuf = (uint32_t)__cvta_generic_to_shared(s_dyn);
    const uint32_t mb0  = (uint32_t)__cvta_generic_to_shared(&s_mbar);

    // ======================= P1: column-sum partials =======================
    // Block b: batch n = b>>6, 32-row slab c = b&63 (128 KB). Issue all 4
    // 32 KB bulk loads at once, wait ONCE, accumulate from SMEM.
    {
        const int n = b >> 6;
        const int c = b & 63;
        const float* __restrict__ slab = vals + (size_t)(n * SLEN + c * 32) * EMB;

        if (tid == 0) {
            mbar_init(mb0, 1);
            asm volatile("fence.proxy.async.shared::cta;" ::: "memory");
            mbar_expect_tx(mb0, SLAB_BYTES);
            #pragma unroll
            for (int r = 0; r < 4; ++r)
                bulk_ld(sbuf + r * 32768, slab + r * 8192, 32768, mb0);
        }
        __syncthreads();
        mbar_wait(mb0, 0);

        // thread (rg = tid>>8, col = tid&255) sums rows rg*8..rg*8+7
        const int rg  = tid >> 8;
        const int col = tid & 255;
        float4 acc = make_float4(0.f, 0.f, 0.f, 0.f);
        #pragma unroll
        for (int s = 0; s < 8; ++s) {
            const float4 v = s_dyn[(rg * 8 + s) * 256 + col];
            acc.x += v.x; acc.y += v.y; acc.z += v.z; acc.w += v.w;
        }
        __syncthreads();               // all reads done before overlay reuse
        s_dyn[tid] = acc;
        __syncthreads();
        if (tid < 256) {
            float4 a0 = s_dyn[tid];
            const float4 a1 = s_dyn[256 + tid];
            const float4 a2 = s_dyn[512 + tid];
            const float4 a3 = s_dyn[768 + tid];
            a0.x = (a0.x + a1.x) + (a2.x + a3.x);
            a0.y = (a0.y + a1.y) + (a2.y + a3.y);
            a0.z = (a0.z + a1.z) + (a2.z + a3.z);
            a0.w = (a0.w + a1.w) + (a2.w + a3.w);
            ((float4*)g_part[n][c])[tid] = a0;
        }
    }
    gbar(&g_c1, &g_f1);

    // ================= P2: reduce partials -> sv, apply Wv =================
    // 32 blocks: (n = b>>4, head h = b&15). 1024 threads = 64 chunks x 16
    // float4 cols; fixed-pairing smem tree. Then 64-thread Wv matvec.
    if (b < 32) {
        const int n = b >> 4;
        const int h = b & 15;
        const int c = tid >> 4;        // chunk 0..63
        const int L = tid & 15;        // float4 col within the head

        s_dyn[c * 16 + L] = __ldcg(&((const float4*)g_part[n][c])[h * 16 + L]);
        __syncthreads();
        #pragma unroll
        for (int st = 32; st >= 1; st >>= 1) {
            if (c < st) {
                float4 a = s_dyn[c * 16 + L], d2 = s_dyn[(c + st) * 16 + L];
                a.x += d2.x; a.y += d2.y; a.z += d2.z; a.w += d2.w;
                s_dyn[c * 16 + L] = a;
            }
            __syncthreads();
        }
        if (tid < 64) {
            const float* __restrict__ svh  = (const float*)s_dyn;  // 64 floats
            const float* __restrict__ wrow = Wv + tid * 64;
            float acc = 0.f;
            #pragma unroll 16
            for (int dp = 0; dp < 64; ++dp) acc += __ldg(&wrow[dp]) * svh[dp];
            g_t[n][h * 64 + tid] = acc;
        }
    }
    gbar(&g_c2, &g_f2);

    // ===================== P3: y = Wo @ t + bo (both n) =====================
    // 128 blocks x 8 e-rows; 4 warps per e split the 1024-wide dot.
    {
        const int e0   = b * 8;
        const int w    = tid >> 5;       // warp 0..31
        const int lane = tid & 31;
        const int el   = w >> 2;         // e-local 0..7
        const int q    = w & 3;          // quarter (64 float4 each)

        const int e = e0 + el;
        const float4* __restrict__ row =
            (const float4*)(Wo + (size_t)e * EMB) + q * 64;
        const float4* __restrict__ t0 = (const float4*)g_t[0] + q * 64;
        const float4* __restrict__ t1 = (const float4*)g_t[1] + q * 64;

        float a0 = 0.f, a1 = 0.f;
        #pragma unroll
        for (int i = lane; i < 64; i += 32) {
            float4 wv = __ldg(&row[i]);
            float4 x  = __ldcg(&t0[i]);
            float4 z  = __ldcg(&t1[i]);
            a0 += wv.x * x.x + wv.y * x.y + wv.z * x.z + wv.w * x.w;
            a1 += wv.x * z.x + wv.y * z.y + wv.z * z.z + wv.w * z.w;
        }
        #pragma unroll
        for (int o = 16; o; o >>= 1) {
            a0 += __shfl_xor_sync(0xFFFFFFFFu, a0, o);
            a1 += __shfl_xor_sync(0xFFFFFFFFu, a1, o);
        }
        if (lane == 0) {
            s_part3[0][el][q] = a0;
            s_part3[1][el][q] = a1;
        }
        __syncthreads();
        if (tid < 16) {                   // n = tid>>3, e-local = tid&7
            const int nn = tid >> 3;
            const int ee = tid & 7;
            g_y[nn][e0 + ee] = ((s_part3[nn][ee][0] + s_part3[nn][ee][1])
                              + (s_part3[nn][ee][2] + s_part3[nn][ee][3]))
                             + __ldg(&bo[e0 + ee]);
        }
    }
    gbar(&g_c3, &g_f3);

    // ===================== P4: broadcast y to all rows =====================
    // Replicate y 8x into 32 KB SMEM, then 4 x 32 KB bulk stores per block.
    {
        const int n = b >> 6;
        const int c = b & 63;

        const float4 vy = __ldcg(&((const float4*)g_y[n])[tid & 255]);
        s_dyn[tid]        = vy;   // rows 0..3
        s_dyn[1024 + tid] = vy;   // rows 4..7
        asm volatile("fence.proxy.async.shared::cta;" ::: "memory");
        __syncthreads();

        if (tid == 0) {
            float* dst = out + (size_t)(n * SLEN + c * 32) * EMB;
            #pragma unroll
            for (int r = 0; r < 4; ++r)
                bulk_st(dst + r * 8192, sbuf, 32768);
            asm volatile("cp.async.bulk.commit_group;" ::: "memory");
            asm volatile("cp.async.bulk.wait_group 0;" ::: "memory");
        }
    }

    // ======================= exit: reset for replay ========================
    __threadfence();
    __syncthreads();
    if (tid == 0) {
        if (atomicAdd(&g_ce, 1) == NBLK - 1) {
            g_c1 = 0; g_c2 = 0; g_c3 = 0; g_ce = 0;
            g_f1 = 0; g_f2 = 0; g_f3 = 0;
        }
    }
}

// ---------------------------------------------------------------------------
// Inputs (metadata order): 0=values 1=keys 2=queries 3=mask 4=Wv 5=Wk 6=Wq
//                          7=Wo 8=bo.   Output: float32 [2, 2048, 1024].
// ---------------------------------------------------------------------------
extern "C" void kernel_launch(void* const* d_in, const int* in_sizes, int n_in,
                              void* d_out, int out_size)
{
    const float* values = (const float*)d_in[0];
    const float* Wv     = (const float*)d_in[4];
    const float* Wo     = (const float*)d_in[7];
    const float* bo     = (const float*)d_in[8];
    float*       out    = (float*)d_out;

    cudaFuncSetAttribute(k_fused, cudaFuncAttributeMaxDynamicSharedMemorySize,
                         SMEM_BYTES);
    k_fused<<<NBLK, THR, SMEM_BYTES>>>(values, Wv, Wo, bo, out);
}